// round 1
// baseline (speedup 1.0000x reference)
#include <cuda_runtime.h>

#define Bsz 4096
#define Isz 256
#define Osz 256
#define Gsz 32
#define SLOTS 65          // 32 cos + 32 sin + 1 silu-base feature slots per i
#define BT 128            // B tile
#define OT 64             // O tile
#define GEMM_SMEM (SLOTS*BT*4 + SLOTS*OT*8)

// scratch (allocation-free rule: __device__ globals)
__device__ float g_c1[Isz * Bsz];      // cos(x)  transposed [i][b]
__device__ float g_s1[Isz * Bsz];      // sin(x)  transposed [i][b]
__device__ float g_base[Isz * Bsz];    // silu(x) transposed [i][b]
__device__ float g_W[Isz * SLOTS * Osz]; // folded weights [i][slot][j]

__device__ __forceinline__ unsigned long long ffma2(unsigned long long a,
                                                    unsigned long long b,
                                                    unsigned long long c) {
    unsigned long long d;
    asm("fma.rn.f32x2 %0, %1, %2, %3;" : "=l"(d) : "l"(a), "l"(b), "l"(c));
    return d;
}

// Kernel 1: per-(b,i) transcendentals, written i-major for coalesced GEMM loads
__global__ void kan_xform(const float* __restrict__ x) {
    int i = blockIdx.y;
    int b = blockIdx.x * blockDim.x + threadIdx.x;
    float v = x[(size_t)b * Isz + i];
    float s, c;
    __sincosf(v, &s, &c);
    g_c1[i * Bsz + b] = c;
    g_s1[i * Bsz + b] = s;
    g_base[i * Bsz + b] = v * (1.0f / (1.0f + __expf(-v)));
}

// Kernel 2: fold mask/scale_fft/scale_base into fouriercoeffs -> W[i][slot][j]
__global__ void kan_prep(const float* __restrict__ fc, const float* __restrict__ mask,
                         const float* __restrict__ sb, const float* __restrict__ sf) {
    int i = blockIdx.x;   // input dim
    int j = threadIdx.x;  // output dim
    float m  = mask[i * Osz + j];
    float wf = sf[i * Osz + j] * m;
    float wb = sb[i * Osz + j] * m;
    const float* f0 = fc + ((size_t)j * Isz + i) * Gsz;            // fc[0][j][i][:]
    const float* f1 = f0 + (size_t)Osz * Isz * Gsz;                // fc[1][j][i][:]
    float* wr = g_W + (size_t)i * SLOTS * Osz;
#pragma unroll
    for (int k = 0; k < Gsz; ++k) {
        wr[k * Osz + j]         = wf * f0[k];   // cos weights
        wr[(Gsz + k) * Osz + j] = wf * f1[k];   // sin weights
    }
    wr[64 * Osz + j] = wb;                      // silu-base weight
}

// Kernel 3: fused feature-generating GEMM, f32x2 packed over b-pairs.
// 256 threads, tile 128b x 64o, thread tile 8b(4 f32x2 pairs) x 4o (strided by 16).
__global__ void __launch_bounds__(256, 1)
kan_gemm(const float* __restrict__ bias, float* __restrict__ out) {
    extern __shared__ float smem[];
    float*  sA = smem;                          // [SLOTS][BT] features
    float2* sW = (float2*)(smem + SLOTS * BT);  // [SLOTS][OT] duplicated (w,w)

    const int b0  = blockIdx.x * BT;
    const int o0  = blockIdx.y * OT;
    const int tid = threadIdx.x;
    const int to  = tid & 15;   // 16 o-groups (strided o: to, to+16, to+32, to+48)
    const int tb  = tid >> 4;   // 16 b-groups of 8 rows

    unsigned long long acc[4][4];
#pragma unroll
    for (int p = 0; p < 4; ++p)
#pragma unroll
        for (int q = 0; q < 4; ++q) acc[p][q] = 0ull;

    for (int i = 0; i < Isz; ++i) {
        __syncthreads();
        if (tid < BT) {
            // warps 0-3: angle-addition recurrence -> 65 feature rows
            int b = tid;
            float c1 = g_c1[i * Bsz + b0 + b];
            float s1 = g_s1[i * Bsz + b0 + b];
            sA[0 * BT + b]  = c1;
            sA[32 * BT + b] = s1;
            sA[64 * BT + b] = g_base[i * Bsz + b0 + b];
            float c = c1, s = s1;
#pragma unroll
            for (int k = 1; k < 32; ++k) {
                float cn = fmaf(c, c1, -(s * s1));   // cos((k+1)x)
                float sn = fmaf(s, c1,   c * s1);    // sin((k+1)x)
                c = cn; s = sn;
                sA[k * BT + b]        = c;
                sA[(32 + k) * BT + b] = s;
            }
        } else {
            // warps 4-7: stage weights (duplicated into f32x2 lanes)
            int t = tid - BT;
            const float4* src = (const float4*)(g_W + (size_t)i * SLOTS * Osz + o0);
#pragma unroll
            for (int it = 0; it < 9; ++it) {
                int idx = t + it * 128;
                if (idx < SLOTS * 16) {
                    int slot = idx >> 4;
                    int f4   = idx & 15;
                    float4 w = src[slot * (Osz / 4) + f4];
                    float2* dst = sW + slot * OT + f4 * 4;
                    dst[0] = make_float2(w.x, w.x);
                    dst[1] = make_float2(w.y, w.y);
                    dst[2] = make_float2(w.z, w.z);
                    dst[3] = make_float2(w.w, w.w);
                }
            }
        }
        __syncthreads();

        // MAC over the 65 feature slots of this i
#pragma unroll 13
        for (int s = 0; s < SLOTS; ++s) {
            const ulonglong2* ap = (const ulonglong2*)(sA + s * BT + tb * 8);
            ulonglong2 A01 = ap[0];              // b pairs {0,1},{2,3}
            ulonglong2 A23 = ap[1];              // b pairs {4,5},{6,7}
            const float2* wrow = sW + s * OT;
#pragma unroll
            for (int q = 0; q < 4; ++q) {
                unsigned long long w =
                    *(const unsigned long long*)(wrow + to + 16 * q);
                acc[0][q] = ffma2(A01.x, w, acc[0][q]);
                acc[1][q] = ffma2(A01.y, w, acc[1][q]);
                acc[2][q] = ffma2(A23.x, w, acc[2][q]);
                acc[3][q] = ffma2(A23.y, w, acc[3][q]);
            }
        }
    }

    // epilogue: unpack b-pairs, add bias
#pragma unroll
    for (int q = 0; q < 4; ++q) {
        int o = o0 + to + 16 * q;
        float bv = bias[o];
#pragma unroll
        for (int p = 0; p < 4; ++p) {
            float2 v = *reinterpret_cast<float2*>(&acc[p][q]);
            int br = b0 + tb * 8 + 2 * p;
            out[(size_t)br * Osz + o]       = v.x + bv;
            out[(size_t)(br + 1) * Osz + o] = v.y + bv;
        }
    }
}

extern "C" void kernel_launch(void* const* d_in, const int* in_sizes, int n_in,
                              void* d_out, int out_size) {
    const float* x    = (const float*)d_in[0];
    const float* fc   = (const float*)d_in[1];
    const float* bias = (const float*)d_in[2];
    const float* mask = (const float*)d_in[3];
    const float* sb   = (const float*)d_in[4];
    const float* sf   = (const float*)d_in[5];
    float* out = (float*)d_out;

    cudaFuncSetAttribute(kan_gemm, cudaFuncAttributeMaxDynamicSharedMemorySize,
                         GEMM_SMEM);

    kan_xform<<<dim3(Bsz / 256, Isz), 256>>>(x);
    kan_prep<<<Isz, Osz>>>(fc, mask, sb, sf);
    kan_gemm<<<dim3(Bsz / BT, Osz / OT), 256, GEMM_SMEM>>>(bias, out);
}